// round 1
// baseline (speedup 1.0000x reference)
#include <cuda_runtime.h>
#include <math_constants.h>

#define D_DIM 64
#define BQ 128
#define BK 32
#define NTHREADS 128

typedef unsigned long long ull;

__device__ __forceinline__ ull fma2(ull a, ull b, ull c) {
    ull d;
    asm("fma.rn.f32x2 %0, %1, %2, %3;" : "=l"(d) : "l"(a), "l"(b), "l"(c));
    return d;
}
__device__ __forceinline__ ull mul2(ull a, ull b) {
    ull d;
    asm("mul.rn.f32x2 %0, %1, %2;" : "=l"(d) : "l"(a), "l"(b));
    return d;
}
__device__ __forceinline__ ull pack2(float lo, float hi) {
    ull d;
    asm("mov.b64 %0, {%1, %2};" : "=l"(d) : "f"(lo), "f"(hi));
    return d;
}
__device__ __forceinline__ float2 unpack2(ull a) {
    float lo, hi;
    asm("mov.b64 {%0, %1}, %2;" : "=f"(lo), "=f"(hi) : "l"(a));
    return make_float2(lo, hi);
}

// One query row per thread. Q and the output accumulator live in registers as
// packed f32x2 pairs; K/V tiles are staged in shared memory and read via
// broadcast LDS.128 (all lanes same address -> conflict-free).
__global__ __launch_bounds__(NTHREADS, 2)
void attn_kernel(const float* __restrict__ Q, const float* __restrict__ K,
                 const float* __restrict__ V, const float* __restrict__ Mask,
                 float* __restrict__ O, int S) {
    __shared__ ull Ks[BK * D_DIM / 2];
    __shared__ ull Vs[BK * D_DIM / 2];

    const int b  = blockIdx.y;
    const int qi = blockIdx.x * BQ + threadIdx.x;            // query row in batch
    const size_t base = (size_t)b * S * D_DIM;

    // fold 1/sqrt(D) and log2(e) into q so softmax uses exp2 (MUFU.EX2)
    const float scale = 0.125f * 1.44269504088896340736f;

    // ---- load q row into packed registers ----
    ull q2[D_DIM / 2];
    {
        const float4* qp = (const float4*)(Q + base + (size_t)qi * D_DIM);
        #pragma unroll
        for (int i = 0; i < D_DIM / 4; i++) {
            float4 t = qp[i];
            q2[2 * i]     = pack2(t.x * scale, t.y * scale);
            q2[2 * i + 1] = pack2(t.z * scale, t.w * scale);
        }
    }

    ull acc2[D_DIM / 2];
    #pragma unroll
    for (int i = 0; i < D_DIM / 2; i++) acc2[i] = 0ull;   // (0.0f, 0.0f)

    float m = -CUDART_INF_F;
    float l = 0.0f;

    for (int kt = 0; kt < S; kt += BK) {
        __syncthreads();
        // ---- cooperative K/V tile load (coalesced float4 == ulonglong2) ----
        {
            const ulonglong2* kp = (const ulonglong2*)(K + base + (size_t)kt * D_DIM);
            const ulonglong2* vp = (const ulonglong2*)(V + base + (size_t)kt * D_DIM);
            #pragma unroll
            for (int i = threadIdx.x; i < BK * D_DIM / 4; i += NTHREADS) {
                ((ulonglong2*)Ks)[i] = kp[i];
                ((ulonglong2*)Vs)[i] = vp[i];
            }
        }
        __syncthreads();

        // ---- scores s[j] = (q*scale) . K[j]  (already in log2 domain) ----
        float s[BK];
        #pragma unroll
        for (int j = 0; j < BK; j++) {
            const ulonglong2* kr = (const ulonglong2*)(Ks + j * (D_DIM / 2));
            ull a0 = 0ull, a1 = 0ull;
            #pragma unroll
            for (int i = 0; i < D_DIM / 4; i++) {
                ulonglong2 t = kr[i];
                a0 = fma2(q2[2 * i],     t.x, a0);
                a1 = fma2(q2[2 * i + 1], t.y, a1);
            }
            float2 f0 = unpack2(a0);
            float2 f1 = unpack2(a1);
            s[j] = (f0.x + f0.y) + (f1.x + f1.y);
        }

        // ---- online softmax update ----
        float mn = m;
        #pragma unroll
        for (int j = 0; j < BK; j++) mn = fmaxf(mn, s[j]);
        float corr = exp2f(m - mn);             // 0 on first tile (m = -inf)
        float ps = 0.0f;
        #pragma unroll
        for (int j = 0; j < BK; j++) {
            float p = exp2f(s[j] - mn);
            s[j] = p;
            ps += p;
        }
        l = l * corr + ps;
        m = mn;

        ull corr2 = pack2(corr, corr);
        #pragma unroll
        for (int i = 0; i < D_DIM / 2; i++) acc2[i] = mul2(acc2[i], corr2);

        // ---- acc += p[j] * V[j] ----
        #pragma unroll
        for (int j = 0; j < BK; j++) {
            const ulonglong2* vr = (const ulonglong2*)(Vs + j * (D_DIM / 2));
            ull pp = pack2(s[j], s[j]);
            #pragma unroll
            for (int i = 0; i < D_DIM / 4; i++) {
                ulonglong2 t = vr[i];
                acc2[2 * i]     = fma2(pp, t.x, acc2[2 * i]);
                acc2[2 * i + 1] = fma2(pp, t.y, acc2[2 * i + 1]);
            }
        }
    }

    // ---- normalize, apply mask, store ----
    float inv = Mask[(size_t)b * S + qi] / l;
    float4* op = (float4*)(O + base + (size_t)qi * D_DIM);
    #pragma unroll
    for (int i = 0; i < D_DIM / 4; i++) {
        float2 f0 = unpack2(acc2[2 * i]);
        float2 f1 = unpack2(acc2[2 * i + 1]);
        float4 t;
        t.x = f0.x * inv; t.y = f0.y * inv;
        t.z = f1.x * inv; t.w = f1.y * inv;
        op[i] = t;
    }
}

extern "C" void kernel_launch(void* const* d_in, const int* in_sizes, int n_in,
                              void* d_out, int out_size) {
    const float* q    = (const float*)d_in[0];
    const float* k    = (const float*)d_in[1];
    const float* v    = (const float*)d_in[2];
    const float* mask = (const float*)d_in[3];
    float* out        = (float*)d_out;

    const int S = 4096;                       // problem shape (B=8, S=4096, D=64)
    const int BS = in_sizes[3];               // B * S
    const int B = BS / S;

    dim3 grid(S / BQ, B);
    attn_kernel<<<grid, NTHREADS>>>(q, k, v, mask, out, S);
}